// round 10
// baseline (speedup 1.0000x reference)
#include <cuda_runtime.h>
#include <cuda_bf16.h>
#include <cstdint>

// GCNStack: out = relu((A @ x) @ W1 + b1) @ W2 + b2  -- mma.sync bf16-split version
//   x:[B,N,64] f32, A COO (idx [2,E] int32/int64 autodetected), val f32
// CSR build + ONE persistent fused kernel (512 thr):
//   warps 8-15: gather y = A@x per 64-node tile -> bf16 hi/lo, swizzled smem (dbl buf)
//   warps 0-7 : GEMM1 (mma.sync, 3-pass split) -> bias/relu/split -> smem h ->
//               GEMM2 (mma.sync, 3-pass split) -> bias -> out

#define B_CONST 4
#define CIN     64
#define HDIM    256
#define COUT    64
#define MAXN    65536
#define MAXE    2000000
#define SCAN_CHUNK 2048
#define MAXBLK  (MAXN / SCAN_CHUNK)

typedef unsigned long long ull;

static __device__ int   g_is64;
static __device__ int   g_counts[MAXN];
static __device__ int   g_rowptr[MAXN + 1];
static __device__ int   g_cursor[MAXN];
static __device__ int   g_part[MAXBLK];
static __device__ int   g_partpre[MAXBLK];
static __device__ int   g_ecol[MAXE];
static __device__ float g_eval[MAXE];

// ================= CSR build =================
__device__ __forceinline__ int idx_row(const void* A, int e, int E, int is64, int N) {
    int r = is64 ? (int)((const long long*)A)[e] : ((const int*)A)[e];
    return r < 0 ? 0 : (r >= N ? N - 1 : r);
}
__device__ __forceinline__ int idx_col(const void* A, int e, int E, int is64, int N) {
    int c = is64 ? (int)((const long long*)A)[(size_t)E + e] : ((const int*)A)[(size_t)E + e];
    return c < 0 ? 0 : (c >= N ? N - 1 : c);
}

__global__ void k_zero(const int* __restrict__ A32, int E, int n) {
    __shared__ int sbad;
    int t = threadIdx.x;
    int i = blockIdx.x * blockDim.x + t;
    if (i < n) g_counts[i] = 0;
    if (blockIdx.x == 0) {
        if (t == 0) sbad = 0;
        __syncthreads();
        int cnt = E < 128 ? E : 128;
        if (t < cnt && A32[2 * t + 1] != 0) sbad = 1;
        __syncthreads();
        if (t == 0) g_is64 = !sbad;
    }
}

__global__ void k_count(const void* __restrict__ A, int E, int N) {
    int e = blockIdx.x * blockDim.x + threadIdx.x;
    if (e < E) atomicAdd(&g_counts[idx_row(A, e, E, g_is64, N)], 1);
}

__global__ __launch_bounds__(256) void k_blocksum(int N) {
    __shared__ int wsum[8];
    int b = blockIdx.x, t = threadIdx.x;
    int base = b * SCAN_CHUNK + t * 8;
    int s = 0;
#pragma unroll
    for (int i = 0; i < 8; i++) { int id = base + i; s += (id < N) ? g_counts[id] : 0; }
#pragma unroll
    for (int o = 16; o > 0; o >>= 1) s += __shfl_down_sync(0xffffffffu, s, o);
    if ((t & 31) == 0) wsum[t >> 5] = s;
    __syncthreads();
    if (t == 0) {
        int tot = 0;
#pragma unroll
        for (int w = 0; w < 8; w++) tot += wsum[w];
        g_part[b] = tot;
    }
}

__global__ void k_scanpart(int nblocks, int E, int N) {
    int lane = threadIdx.x;
    int v = (lane < nblocks) ? g_part[lane] : 0;
    int incl = v;
#pragma unroll
    for (int o = 1; o < 32; o <<= 1) {
        int u = __shfl_up_sync(0xffffffffu, incl, o);
        if (lane >= o) incl += u;
    }
    if (lane < nblocks) g_partpre[lane] = incl - v;
    if (lane == 0) g_rowptr[N] = E;
}

__global__ __launch_bounds__(256) void k_blockscan(int N) {
    __shared__ int wsum[8];
    int b = blockIdx.x, t = threadIdx.x;
    int lane = t & 31, w = t >> 5;
    int base = b * SCAN_CHUNK + t * 8;
    int v[8];
    int s = 0;
#pragma unroll
    for (int i = 0; i < 8; i++) {
        int id = base + i;
        v[i] = (id < N) ? g_counts[id] : 0;
        s += v[i];
    }
    int incl = s;
#pragma unroll
    for (int o = 1; o < 32; o <<= 1) {
        int u = __shfl_up_sync(0xffffffffu, incl, o);
        if (lane >= o) incl += u;
    }
    if (lane == 31) wsum[w] = incl;
    __syncthreads();
    if (w == 0 && lane < 8) {
        int z = wsum[lane];
#pragma unroll
        for (int o = 1; o < 8; o <<= 1) {
            int u = __shfl_up_sync(0xffu, z, o);
            if (lane >= o) z += u;
        }
        wsum[lane] = z;
    }
    __syncthreads();
    int run = g_partpre[b] + (incl - s) + (w ? wsum[w - 1] : 0);
#pragma unroll
    for (int i = 0; i < 8; i++) {
        int id = base + i;
        if (id < N) { g_rowptr[id] = run; g_cursor[id] = run; run += v[i]; }
    }
}

__global__ void k_scatter(const void* __restrict__ A, const float* __restrict__ A_val,
                          int E, int N) {
    int e = blockIdx.x * blockDim.x + threadIdx.x;
    if (e >= E) return;
    int is64 = g_is64;
    int r = idx_row(A, e, E, is64, N);
    int p = atomicAdd(&g_cursor[r], 1);
    g_ecol[p] = idx_col(A, e, E, is64, N);
    g_eval[p] = A_val[e];
}

// ================= mma.sync helpers =================
__device__ __forceinline__ void mma16816(float* c, uint32_t a0, uint32_t a1,
                                         uint32_t a2, uint32_t a3,
                                         uint32_t b0, uint32_t b1) {
    asm volatile(
        "mma.sync.aligned.m16n8k16.row.col.f32.bf16.bf16.f32 "
        "{%0,%1,%2,%3}, {%4,%5,%6,%7}, {%8,%9}, {%0,%1,%2,%3};"
        : "+f"(c[0]), "+f"(c[1]), "+f"(c[2]), "+f"(c[3])
        : "r"(a0), "r"(a1), "r"(a2), "r"(a3), "r"(b0), "r"(b1));
}
__device__ __forceinline__ void ldsm4(uint32_t* r, uint32_t addr) {
    asm volatile("ldmatrix.sync.aligned.m8n8.x4.shared.b16 {%0,%1,%2,%3}, [%4];"
                 : "=r"(r[0]), "=r"(r[1]), "=r"(r[2]), "=r"(r[3]) : "r"(addr));
}
__device__ __forceinline__ void ldsm4t(uint32_t* r, uint32_t addr) {
    asm volatile("ldmatrix.sync.aligned.m8n8.x4.trans.shared.b16 {%0,%1,%2,%3}, [%4];"
                 : "=r"(r[0]), "=r"(r[1]), "=r"(r[2]), "=r"(r[3]) : "r"(addr));
}

#define CVT_BF16X2(res, a, b) \
    asm("cvt.rn.satfinite.bf16x2.f32 %0, %1, %2;" : "=r"(res) : "f"(b), "f"(a))
__device__ __forceinline__ float bfLoF(uint32_t p) { return __uint_as_float(p << 16); }
__device__ __forceinline__ float bfHiF(uint32_t p) { return __uint_as_float(p & 0xFFFF0000u); }

// ---- smem layout (bytes) ----
// W1h/W1l: [k=64][n=256] bf16, 512B rows, chunk^=(k&7) swizzle
// W2h/W2l: [k=256][n=64] bf16, 128B rows
// HH/HL:   [r=64][k=256] bf16, 512B rows
// Y:       2 buffers x (yh [64][64] 8KB + yl 8KB), 128B rows
#define OFF_W1H 0
#define OFF_W1L 32768
#define OFF_W2H 65536
#define OFF_W2L 98304
#define OFF_HH  131072
#define OFF_HL  163840
#define OFF_Y   196608
#define OFF_B1  229376
#define OFF_B2  230400
#define SMEM_FUSED 230656

// ================= fused gather + tensor MLP =================
__global__ __launch_bounds__(512, 1) void k_fused(
    const float* __restrict__ x,
    const float* __restrict__ W1, const float* __restrict__ b1,
    const float* __restrict__ W2, const float* __restrict__ b2,
    float* __restrict__ out, int N)
{
    extern __shared__ char smc[];
    uint32_t sbase;
    asm("{ .reg .u64 tt; cvta.to.shared.u64 tt, %1; cvt.u32.u64 %0, tt; }"
        : "=r"(sbase) : "l"(smc));

    int t = threadIdx.x;
    int w = t >> 5;
    int l = t & 31;
    bool isCompute = (w < 8);

    int nT = (N + 63) >> 6;
    int total = nT * B_CONST;
    float* sB1f = (float*)(smc + OFF_B1);
    float* sB2f = (float*)(smc + OFF_B2);

    // -------- gather: y for tile -> bf16 hi/lo swizzled smem --------
    auto gather_tile = [&](int tile, int buf) {
        int gt = t - 256;
        int hw = gt >> 4, lh = gt & 15;
        int bI = tile & 3;
        int n0 = (tile >> 2) << 6;
        const float4* xb = (const float4*)x + (size_t)bI * N * 16 + lh;
        char* yh = smc + OFF_Y + buf * 16384;
        char* yl = yh + 8192;
#pragma unroll
        for (int j = 0; j < 4; j++) {
            int r = hw * 4 + j;
            int node = n0 + r;
            float4 acc = make_float4(0.f, 0.f, 0.f, 0.f);
            if (node < N) {
                int beg = g_rowptr[node], end = g_rowptr[node + 1];
                int i = beg;
                for (; i + 4 <= end; i += 4) {
                    int   c0 = g_ecol[i],     c1 = g_ecol[i + 1];
                    int   c2 = g_ecol[i + 2], c3 = g_ecol[i + 3];
                    float v0 = g_eval[i],     v1 = g_eval[i + 1];
                    float v2 = g_eval[i + 2], v3 = g_eval[i + 3];
                    float4 p0 = xb[(size_t)c0 * 16], p1 = xb[(size_t)c1 * 16];
                    float4 p2 = xb[(size_t)c2 * 16], p3 = xb[(size_t)c3 * 16];
                    acc.x += v0 * p0.x; acc.y += v0 * p0.y; acc.z += v0 * p0.z; acc.w += v0 * p0.w;
                    acc.x += v1 * p1.x; acc.y += v1 * p1.y; acc.z += v1 * p1.z; acc.w += v1 * p1.w;
                    acc.x += v2 * p2.x; acc.y += v2 * p2.y; acc.z += v2 * p2.z; acc.w += v2 * p2.w;
                    acc.x += v3 * p3.x; acc.y += v3 * p3.y; acc.z += v3 * p3.z; acc.w += v3 * p3.w;
                }
                for (; i < end; i++) {
                    int c = g_ecol[i]; float v = g_eval[i];
                    float4 p = xb[(size_t)c * 16];
                    acc.x += v * p.x; acc.y += v * p.y; acc.z += v * p.z; acc.w += v * p.w;
                }
            }
            uint32_t h01, h23, l01, l23;
            CVT_BF16X2(h01, acc.x, acc.y);
            CVT_BF16X2(h23, acc.z, acc.w);
            float rx = acc.x - bfLoF(h01), ry = acc.y - bfHiF(h01);
            float rz = acc.z - bfLoF(h23), rw = acc.w - bfHiF(h23);
            CVT_BF16X2(l01, rx, ry);
            CVT_BF16X2(l23, rz, rw);
            uint32_t off = (uint32_t)(r * 128 + (((lh >> 1) ^ (r & 7)) << 4) + ((lh & 1) << 3));
            *(ull*)(yh + off) = (ull)h01 | ((ull)h23 << 32);
            *(ull*)(yl + off) = (ull)l01 | ((ull)l23 << 32);
        }
    };

    // -------- prologue --------
    if (isCompute) {
        for (int i = t; i < 64 * 256; i += 256) {            // W1 [k][n]
            int k = i >> 8, n = i & 255;
            float v = W1[i];
            __nv_bfloat16 hh = __float2bfloat16(v);
            __nv_bfloat16 ll = __float2bfloat16(v - __bfloat162float(hh));
            uint32_t off = (uint32_t)(k * 512 + (((n >> 3) ^ (k & 7)) << 4) + ((n & 7) << 1));
            *(__nv_bfloat16*)(smc + OFF_W1H + off) = hh;
            *(__nv_bfloat16*)(smc + OFF_W1L + off) = ll;
        }
        for (int i = t; i < 256 * 64; i += 256) {            // W2 [k][n]
            int k = i >> 6, n = i & 63;
            float v = W2[i];
            __nv_bfloat16 hh = __float2bfloat16(v);
            __nv_bfloat16 ll = __float2bfloat16(v - __bfloat162float(hh));
            uint32_t off = (uint32_t)(k * 128 + (((n >> 3) ^ (k & 7)) << 4) + ((n & 7) << 1));
            *(__nv_bfloat16*)(smc + OFF_W2H + off) = hh;
            *(__nv_bfloat16*)(smc + OFF_W2L + off) = ll;
        }
        if (t < HDIM) sB1f[t] = b1[t];
        if (t < COUT) sB2f[t] = b2[t];
    } else {
        if ((int)blockIdx.x < total) gather_tile(blockIdx.x, 0);
    }
    __syncthreads();

    int r0  = (w & 3) * 16;       // warp's 16-row block
    int cb1 = (w >> 2) * 128;     // GEMM1 col half
    int cb2 = (w >> 2) * 32;      // GEMM2 col half

    int buf = 0;
    for (int tile = blockIdx.x; tile < total; tile += gridDim.x, buf ^= 1) {
        if (isCompute) {
            int bI = tile & 3;
            int n0 = (tile >> 2) << 6;

            // ---- GEMM1: h[64,256] = y @ W1, 3-pass bf16 split ----
            float acc[16][4];
#pragma unroll
            for (int j = 0; j < 16; j++) {
                acc[j][0] = 0.f; acc[j][1] = 0.f; acc[j][2] = 0.f; acc[j][3] = 0.f;
            }
            uint32_t yB = sbase + OFF_Y + (uint32_t)buf * 16384u;
#pragma unroll
            for (int pass = 0; pass < 3; pass++) {
                uint32_t aB = yB + (pass == 2 ? 8192u : 0u);
                uint32_t bB = sbase + (pass == 1 ? OFF_W1L : OFF_W1H);
#pragma unroll
                for (int ki = 0; ki < 4; ki++) {
                    int k0 = ki * 16;
                    uint32_t ar = (uint32_t)(r0 + (l & 7) + (l & 8));
                    uint32_t ac = (uint32_t)(k0 >> 3) + (uint32_t)(l >> 4);
                    uint32_t a[4];
                    ldsm4(a, aB + ar * 128 + ((ac ^ (ar & 7)) << 4));
                    uint32_t br = (uint32_t)(k0 + (l & 7) + (l & 8));
#pragma unroll
                    for (int j = 0; j < 8; j++) {
                        uint32_t bc = (uint32_t)((cb1 + 16 * j) >> 3) + (uint32_t)(l >> 4);
                        uint32_t b[4];
                        ldsm4t(b, bB + br * 512 + ((bc ^ (br & 7)) << 4));
                        mma16816(acc[2 * j],     a[0], a[1], a[2], a[3], b[0], b[1]);
                        mma16816(acc[2 * j + 1], a[0], a[1], a[2], a[3], b[2], b[3]);
                    }
                }
            }

            // ---- epi1: bias + relu + bf16 split -> HH/HL ----
            {
                int ca = 2 * (l & 3);
                int ra = r0 + (l >> 2), rb = ra + 8;
#pragma unroll
                for (int j = 0; j < 16; j++) {
                    int c = cb1 + 8 * j + ca;
                    float2 bb = *(float2*)&sB1f[c];
                    float h0 = fmaxf(acc[j][0] + bb.x, 0.f);
                    float h1 = fmaxf(acc[j][1] + bb.y, 0.f);
                    float h2 = fmaxf(acc[j][2] + bb.x, 0.f);
                    float h3 = fmaxf(acc[j][3] + bb.y, 0.f);
                    uint32_t hh, hl;
                    CVT_BF16X2(hh, h0, h1);
                    float q0 = h0 - bfLoF(hh), q1 = h1 - bfHiF(hh);
                    CVT_BF16X2(hl, q0, q1);
                    uint32_t offA = (uint32_t)(ra * 512 + ((((c >> 3)) ^ (ra & 7)) << 4) + ((c & 7) << 1));
                    *(uint32_t*)(smc + OFF_HH + offA) = hh;
                    *(uint32_t*)(smc + OFF_HL + offA) = hl;
                    CVT_BF16X2(hh, h2, h3);
                    q0 = h2 - bfLoF(hh); q1 = h3 - bfHiF(hh);
                    CVT_BF16X2(hl, q0, q1);
                    uint32_t offB = (uint32_t)(rb * 512 + ((((c >> 3)) ^ (rb & 7)) << 4) + ((c & 7) << 1));
                    *(uint32_t*)(smc + OFF_HH + offB) = hh;
                    *(uint32_t*)(smc + OFF_HL + offB) = hl;
                }
            }
            asm volatile("bar.sync 1, 256;" ::: "memory");   // compute warps only

            // ---- GEMM2: out[64,64] = h @ W2, 3-pass bf16 split ----
            float a2[4][4];
#pragma unroll
            for (int j = 0; j < 4; j++) {
                a2[j][0] = 0.f; a2[j][1] = 0.f; a2[j][2] = 0.f; a2[j][3] = 0.f;
            }
#pragma unroll
            for (int pass = 0; pass < 3; pass++) {
                uint32_t aB = sbase + (pass == 2 ? OFF_HL : OFF_HH);
                uint32_t bB = sbase + (pass == 1 ? OFF_W2L : OFF_W2H);
                for (int ki = 0; ki < 16; ki++) {
                    int k0 = ki * 16;
                    uint32_t ar = (uint32_t)(r0 + (l & 7) + (l & 8));
                    uint32_t ac = (uint32_t)(k0 >> 3) + (uint32_t)(l >> 4);
                    uint32_t a[4];
                    ldsm4(a, aB + ar * 512 + ((ac ^ (ar & 7)) << 4));
                    uint32_t br = (uint32_t)(k0 + (l & 7) + (l & 8));
#pragma unroll
                    for (int j = 0; j < 2; j++) {
                        uint32_t bc = (uint32_t)((cb2 + 16 * j) >> 3) + (uint32_t)(l >> 4);
                        uint32_t b[4];
                        ldsm4t(b, bB + br * 128 + ((bc ^ (br & 7)) << 4));
                        mma16816(a2[2 * j],     a[0], a[1], a[2], a[3], b[0], b[1]);
                        mma16816(a2[2 * j + 1], a[0], a[1], a[2], a[3], b[2], b[3]);
                    }
                }
            }

            // ---- epi2: bias -> out ----
            {
                int ca = 2 * (l & 3);
                int rowA = n0 + r0 + (l >> 2);
                int rowB = rowA + 8;
#pragma unroll
                for (int j = 0; j < 4; j++) {
                    int c = cb2 + 8 * j + ca;
                    float2 bb = *(float2*)&sB2f[c];
                    if (rowA < N) {
                        float2 o = make_float2(a2[j][0] + bb.x, a2[j][1] + bb.y);
                        *(float2*)&out[((size_t)bI * N + rowA) * COUT + c] = o;
                    }
                    if (rowB < N) {
                        float2 o = make_float2(a2[j][2] + bb.x, a2[j][3] + bb.y);
                        *(float2*)&out[((size_t)bI * N + rowB) * COUT + c] = o;
                    }
                }
            }
        } else {
            int next = tile + gridDim.x;
            if (next < total) gather_tile(next, buf ^ 1);
        }
        __syncthreads();   // y[buf] consumed; y[buf^1] ready; h safe for next epi1
    }
}

// ================= launch =================
extern "C" void kernel_launch(void* const* d_in, const int* in_sizes, int n_in,
                              void* d_out, int out_size) {
    const float* x  = (const float*)d_in[0];
    const void*  A  = d_in[1];
    const float* Av = (const float*)d_in[2];
    const float* W1 = (const float*)d_in[3];
    const float* b1 = (const float*)d_in[4];
    const float* W2 = (const float*)d_in[5];
    const float* b2 = (const float*)d_in[6];
    float* out = (float*)d_out;

    int E = in_sizes[1] / 2;
    int N = in_sizes[0] / (B_CONST * CIN);
    int nb = (N + SCAN_CHUNK - 1) / SCAN_CHUNK;

    k_zero<<<(N + 255) / 256, 256>>>((const int*)A, E, N);
    k_count<<<(E + 255) / 256, 256>>>(A, E, N);
    k_blocksum<<<nb, 256>>>(N);
    k_scanpart<<<1, 32>>>(nb, E, N);
    k_blockscan<<<nb, 256>>>(N);
    k_scatter<<<(E + 255) / 256, 256>>>(A, Av, E, N);

    cudaFuncSetAttribute(k_fused, cudaFuncAttributeMaxDynamicSharedMemorySize, SMEM_FUSED);
    k_fused<<<148, 512, SMEM_FUSED>>>(x, W1, b1, W2, b2, out, N);
}